// round 9
// baseline (speedup 1.0000x reference)
#include <cuda_runtime.h>
#include <cuda_bf16.h>

#define SEQLEN  512
#define T_TOT   513
#define EMB     256
#define HID     512
#define G4H     2048
#define VOCAB   32000
#define NLSTM   64
#define NGEMM   84
#define GRID_K2 (NLSTM + NGEMM)   // 148 = one CTA per SM
#define SOS_ID  1
#define FSTR    32                // one 128B line per flag

#define NTILE_N 250
#define NTILES  (5 * NTILE_N)     // 1000 MMA tiles + 250 GEMV slices

#define KC      32
#define PADW    40
#define TILE_E  (128 * PADW)
#define HALF_BYTES (8 * TILE_E * 2 + 128)
#define SMEM_K2    (2 * HALF_BYTES)

// ---------------- scratch ----------------
__device__ float g_emb[T_TOT * EMB];
__device__ float g_bias[G4H];
__device__ float g_X[T_TOT * G4H];
__device__ unsigned long long g_pub[T_TOT * HID];   // {f32 h, u32 tag=t+1}
__device__ __nv_bfloat16 g_Ahi[T_TOT * HID];
__device__ __nv_bfloat16 g_Alo[T_TOT * HID];
__device__ __nv_bfloat16 g_Whi[VOCAB * HID];
__device__ __nv_bfloat16 g_Wlo[VOCAB * HID];
__device__ int g_done[NLSTM * FSTR];
__device__ int g_qhead;
__device__ int g_cvt;

#define NB(id) asm volatile("bar.sync %0, 256;" :: "r"(id) : "memory")

__device__ __forceinline__ float tanh_f(float x) {
    float y; asm("tanh.approx.f32 %0, %1;" : "=f"(y) : "f"(x)); return y;
}

// ---------------- K0: gather emb, bias sum, clear state ----------------
__global__ void setup_kernel(const int* __restrict__ seq,
                             const float* __restrict__ emb_table,
                             const float* __restrict__ b_ih,
                             const float* __restrict__ b_hh) {
    int b = blockIdx.x, t = threadIdx.x;   // blockDim == 256
    if (b < T_TOT) {
        int tok = (b == 0) ? SOS_ID : seq[b - 1];
        g_emb[b * EMB + t] = emb_table[tok * EMB + t];
        if (b == 0) {
            if (t < NLSTM) g_done[t * FSTR] = 0;
            if (t == 64) g_qhead = 0;
            if (t == 65) g_cvt = 0;
        }
    } else {
        int i = (b - T_TOT) * 256 + t;
        g_bias[i] = b_ih[i] + b_hh[i];
    }
    const int NW = T_TOT * HID;
    for (int i = b * 256 + t; i < NW; i += gridDim.x * 256) g_pub[i] = 0ULL;
}

// ---------------- FFMA SGEMM for K1 (small) ----------------
__global__ void __launch_bounds__(256) sgemm_kernel(const float* __restrict__ A,
                                                    const float* __restrict__ B,
                                                    const float* __restrict__ bias,
                                                    float* __restrict__ C,
                                                    int M, int N, int K) {
    __shared__ __align__(16) float As[8][128];
    __shared__ __align__(16) float Bs[8][128];
    int bn = blockIdx.x * 128, bm = blockIdx.y * 128;
    int tid = threadIdx.x;
    int lrow = tid >> 1, lk = (tid & 1) * 4;
    int tx = tid & 15, ty = tid >> 4;

    const float* Aptr = A + (size_t)(bm + lrow) * K + lk;
    const float* Bptr = B + (size_t)(bn + lrow) * K + lk;
    bool aval = (bm + lrow) < M;
    float4 av = aval ? *(const float4*)Aptr : make_float4(0.f, 0.f, 0.f, 0.f);
    float4 bv = *(const float4*)Bptr;

    float acc[8][8];
#pragma unroll
    for (int i = 0; i < 8; i++)
#pragma unroll
        for (int j = 0; j < 8; j++) acc[i][j] = 0.f;

    for (int k0 = 0; k0 < K; k0 += 8) {
        As[lk + 0][lrow] = av.x; As[lk + 1][lrow] = av.y;
        As[lk + 2][lrow] = av.z; As[lk + 3][lrow] = av.w;
        Bs[lk + 0][lrow] = bv.x; Bs[lk + 1][lrow] = bv.y;
        Bs[lk + 2][lrow] = bv.z; Bs[lk + 3][lrow] = bv.w;
        __syncthreads();
        if (k0 + 8 < K) {
            av = aval ? *(const float4*)(Aptr + k0 + 8) : make_float4(0.f, 0.f, 0.f, 0.f);
            bv = *(const float4*)(Bptr + k0 + 8);
        }
#pragma unroll
        for (int k = 0; k < 8; k++) {
            float ar[8], br[8];
            *(float4*)(ar)     = *(const float4*)&As[k][ty * 8];
            *(float4*)(ar + 4) = *(const float4*)&As[k][ty * 8 + 4];
            *(float4*)(br)     = *(const float4*)&Bs[k][tx * 8];
            *(float4*)(br + 4) = *(const float4*)&Bs[k][tx * 8 + 4];
#pragma unroll
            for (int i = 0; i < 8; i++)
#pragma unroll
                for (int j = 0; j < 8; j++)
                    acc[i][j] = fmaf(ar[i], br[j], acc[i][j]);
        }
        __syncthreads();
    }
    float4 bb0 = *(const float4*)&bias[bn + tx * 8];
    float4 bb1 = *(const float4*)&bias[bn + tx * 8 + 4];
#pragma unroll
    for (int i = 0; i < 8; i++) {
        int m = bm + ty * 8 + i;
        if (m < M) {
            float4 o0 = make_float4(acc[i][0] + bb0.x, acc[i][1] + bb0.y,
                                    acc[i][2] + bb0.z, acc[i][3] + bb0.w);
            float4 o1 = make_float4(acc[i][4] + bb1.x, acc[i][5] + bb1.y,
                                    acc[i][6] + bb1.z, acc[i][7] + bb1.w);
            *(float4*)&C[(size_t)m * N + bn + tx * 8]     = o0;
            *(float4*)&C[(size_t)m * N + bn + tx * 8 + 4] = o1;
        }
    }
}

// ---------------- GEMM helpers ----------------
__device__ __forceinline__ void cp_async16(unsigned dst, const void* src, int sz) {
    asm volatile("cp.async.ca.shared.global [%0], [%1], 16, %2;\n"
                 :: "r"(dst), "l"(src), "r"(sz));
}
__device__ __forceinline__ void mma16(float* c, const unsigned* a, const unsigned* b) {
    asm volatile("mma.sync.aligned.m16n8k16.row.col.f32.bf16.bf16.f32 "
                 "{%0,%1,%2,%3}, {%4,%5,%6,%7}, {%8,%9}, {%0,%1,%2,%3};"
                 : "+f"(c[0]), "+f"(c[1]), "+f"(c[2]), "+f"(c[3])
                 : "r"(a[0]), "r"(a[1]), "r"(a[2]), "r"(a[3]),
                   "r"(b[0]), "r"(b[1]));
}

// ---------------- persistent GEMM worker (one 256-thread pipeline) ----------------
__device__ void gemm_worker(char* sm, int bar_id, int htid,
                            const float* __restrict__ bias, float* __restrict__ C) {
    __nv_bfloat16* Ah = (__nv_bfloat16*)sm;
    __nv_bfloat16* Al = Ah + 2 * TILE_E;
    __nv_bfloat16* Bh = Ah + 4 * TILE_E;
    __nv_bfloat16* Bl = Ah + 6 * TILE_E;
    volatile int* q_slot = (volatile int*)(sm + 8 * TILE_E * 2);

    int warp = htid >> 5, lane = htid & 31;
    int wm = warp >> 2, wn = warp & 3;
    int group = lane >> 2, tg = lane & 3;

    if (htid == 0) {
        int v;
        do {
            asm volatile("ld.acquire.gpu.global.s32 %0, [%1];"
                         : "=r"(v) : "l"(&g_cvt) : "memory");
        } while (v < NGEMM);
    }
    NB(bar_id);

    for (;;) {
        if (htid == 0) *q_slot = atomicAdd(&g_qhead, 1);
        NB(bar_id);
        int q = *q_slot;
        if (q >= NTILES) return;
        int band = q / NTILE_N;
        int need = min((band + 1) * 128, T_TOT);

        // band readiness: all 64 lstm CTAs past 'need' steps
        if (htid < 32) {
            int v1, v2;
            do {
                asm volatile("ld.acquire.gpu.global.s32 %0, [%1];"
                             : "=r"(v1) : "l"(&g_done[htid * FSTR]) : "memory");
                asm volatile("ld.acquire.gpu.global.s32 %0, [%1];"
                             : "=r"(v2) : "l"(&g_done[(htid + 32) * FSTR]) : "memory");
            } while (__any_sync(0xffffffffu, (v1 < need) || (v2 < need)));
        }
        NB(bar_id);

        if (band == 4) {
            // ---- GEMV slice: logits row SEQLEN (final h), 128 columns ----
            int col0 = (q - 4 * NTILE_N) * 128;
            float* hsm = (float*)sm;
            for (int i = htid; i < HID; i += 256) {
                unsigned long long p = g_pub[(size_t)SEQLEN * HID + i];
                hsm[i] = __uint_as_float((unsigned)p);
            }
            NB(bar_id);
            int col  = col0 + (htid >> 1);
            int half = htid & 1;
            const __nv_bfloat16* ph = g_Whi + (size_t)col * HID + half * 256;
            const __nv_bfloat16* pl = g_Wlo + (size_t)col * HID + half * 256;
            const float* hh = hsm + half * 256;
            float acc = 0.f;
#pragma unroll 4
            for (int k = 0; k < 256; k += 8) {
                uint4 uh = *(const uint4*)(ph + k);
                uint4 ul = *(const uint4*)(pl + k);
                const unsigned* uhp = &uh.x;
                const unsigned* ulp = &ul.x;
#pragma unroll
                for (int j = 0; j < 4; j++) {
                    float2 fh = __bfloat1622float2(*(const __nv_bfloat162*)&uhp[j]);
                    float2 fl = __bfloat1622float2(*(const __nv_bfloat162*)&ulp[j]);
                    acc = fmaf(fh.x + fl.x, hh[k + 2 * j], acc);
                    acc = fmaf(fh.y + fl.y, hh[k + 2 * j + 1], acc);
                }
            }
            float other = __shfl_down_sync(0xffffffffu, acc, 1);
            if (!half) C[(size_t)SEQLEN * VOCAB + col] = acc + other + bias[col];
            NB(bar_id);   // protect hsm before next round's cp.async
            continue;
        }

        int bn = (q - band * NTILE_N) * 128;
        int bm = band * 128;

        auto load_stage = [&](int s, int kc) {
#pragma unroll
            for (int i = 0; i < 2; i++) {
                int id  = htid + i * 256;
                int row = id >> 2;
                int kk  = (id & 3) * 8;
                unsigned so = (unsigned)(s * TILE_E + row * PADW + kk) * 2;
                unsigned base = (unsigned)__cvta_generic_to_shared(sm);
                cp_async16(base + so,                  g_Ahi + (size_t)(bm + row) * HID + kc + kk, 16);
                cp_async16(base + so + 2 * TILE_E * 2, g_Alo + (size_t)(bm + row) * HID + kc + kk, 16);
                cp_async16(base + so + 4 * TILE_E * 2, g_Whi + (size_t)(bn + row) * HID + kc + kk, 16);
                cp_async16(base + so + 6 * TILE_E * 2, g_Wlo + (size_t)(bn + row) * HID + kc + kk, 16);
            }
            asm volatile("cp.async.commit_group;\n");
        };

        float acc[4][4][4];
#pragma unroll
        for (int mt = 0; mt < 4; mt++)
#pragma unroll
            for (int nt = 0; nt < 4; nt++)
#pragma unroll
                for (int e = 0; e < 4; e++) acc[mt][nt][e] = 0.f;

        const int NCH = HID / KC;   // 16
        load_stage(0, 0);

        for (int c = 0; c < NCH; c++) {
            if (c + 1 < NCH) {
                load_stage((c + 1) & 1, (c + 1) * KC);
                asm volatile("cp.async.wait_group 1;\n");
            } else {
                asm volatile("cp.async.wait_group 0;\n");
            }
            NB(bar_id);

            int s = c & 1;
#pragma unroll
            for (int ks = 0; ks < 2; ks++) {
                int k0 = ks * 16 + tg * 2;
                unsigned aH[4][4], aL[4][4], bHf[4][2], bLf[4][2];
#pragma unroll
                for (int mt = 0; mt < 4; mt++) {
                    int r0 = (wm * 64 + mt * 16 + group) * PADW + s * TILE_E;
                    aH[mt][0] = *(const unsigned*)&Ah[r0 + k0];
                    aH[mt][1] = *(const unsigned*)&Ah[r0 + 8 * PADW + k0];
                    aH[mt][2] = *(const unsigned*)&Ah[r0 + k0 + 8];
                    aH[mt][3] = *(const unsigned*)&Ah[r0 + 8 * PADW + k0 + 8];
                    aL[mt][0] = *(const unsigned*)&Al[r0 + k0];
                    aL[mt][1] = *(const unsigned*)&Al[r0 + 8 * PADW + k0];
                    aL[mt][2] = *(const unsigned*)&Al[r0 + k0 + 8];
                    aL[mt][3] = *(const unsigned*)&Al[r0 + 8 * PADW + k0 + 8];
                }
#pragma unroll
                for (int nt = 0; nt < 4; nt++) {
                    int c0 = (wn * 32 + nt * 8 + group) * PADW + s * TILE_E;
                    bHf[nt][0] = *(const unsigned*)&Bh[c0 + k0];
                    bHf[nt][1] = *(const unsigned*)&Bh[c0 + k0 + 8];
                    bLf[nt][0] = *(const unsigned*)&Bl[c0 + k0];
                    bLf[nt][1] = *(const unsigned*)&Bl[c0 + k0 + 8];
                }
#pragma unroll
                for (int mt = 0; mt < 4; mt++)
#pragma unroll
                    for (int nt = 0; nt < 4; nt++) {
                        mma16(acc[mt][nt], aH[mt], bHf[nt]);
                        mma16(acc[mt][nt], aH[mt], bLf[nt]);
                        mma16(acc[mt][nt], aL[mt], bHf[nt]);
                    }
            }
            NB(bar_id);
        }

#pragma unroll
        for (int nt = 0; nt < 4; nt++) {
            int col = bn + wn * 32 + nt * 8 + tg * 2;
            float b0 = bias[col], b1 = bias[col + 1];
#pragma unroll
            for (int mt = 0; mt < 4; mt++) {
                int row = bm + wm * 64 + mt * 16 + group;
                if (row < T_TOT) {
                    float2 o = make_float2(acc[mt][nt][0] + b0, acc[mt][nt][1] + b1);
                    *(float2*)&C[(size_t)row * VOCAB + col] = o;
                }
                if (row + 8 < T_TOT) {
                    float2 o = make_float2(acc[mt][nt][2] + b0, acc[mt][nt][3] + b1);
                    *(float2*)&C[(size_t)(row + 8) * VOCAB + col] = o;
                }
            }
        }
    }
}

// ---------------- K2 mega-kernel: recurrence + overlapped logits GEMM ------------
extern __shared__ __align__(16) char dsm[];

__global__ void __launch_bounds__(512, 1) fused_kernel(const float* __restrict__ Whh,
                                                       const float* __restrict__ h0,
                                                       const float* __restrict__ c0,
                                                       const float* __restrict__ Wout,
                                                       const float* __restrict__ b_out,
                                                       float* __restrict__ out,
                                                       float* __restrict__ out_tail) {
    int tid = threadIdx.x;

    if (blockIdx.x >= NLSTM) {
        // ============ GEMM CTA: convert W_out, then two tile pipelines ============
        int cb = blockIdx.x - NLSTM;
        const float4* src = (const float4*)Wout;
        const int total4 = VOCAB * HID / 4;
        for (int i = cb * 512 + tid; i < total4; i += NGEMM * 512) {
            float4 v = src[i];
            __nv_bfloat16 h0b = __float2bfloat16(v.x);
            __nv_bfloat16 h1b = __float2bfloat16(v.y);
            __nv_bfloat16 h2b = __float2bfloat16(v.z);
            __nv_bfloat16 h3b = __float2bfloat16(v.w);
            __nv_bfloat16 l0b = __float2bfloat16(v.x - __bfloat162float(h0b));
            __nv_bfloat16 l1b = __float2bfloat16(v.y - __bfloat162float(h1b));
            __nv_bfloat16 l2b = __float2bfloat16(v.z - __bfloat162float(h2b));
            __nv_bfloat16 l3b = __float2bfloat16(v.w - __bfloat162float(h3b));
            uint2 uh, ul;
            uh.x = ((unsigned)__bfloat16_as_ushort(h1b) << 16) | __bfloat16_as_ushort(h0b);
            uh.y = ((unsigned)__bfloat16_as_ushort(h3b) << 16) | __bfloat16_as_ushort(h2b);
            ul.x = ((unsigned)__bfloat16_as_ushort(l1b) << 16) | __bfloat16_as_ushort(l0b);
            ul.y = ((unsigned)__bfloat16_as_ushort(l3b) << 16) | __bfloat16_as_ushort(l2b);
            *(uint2*)&g_Whi[4 * (size_t)i] = uh;
            *(uint2*)&g_Wlo[4 * (size_t)i] = ul;
        }
        __syncthreads();
        if (tid == 0) {
            asm volatile("fence.acq_rel.gpu;" ::: "memory");
            atomicAdd(&g_cvt, 1);
        }
        if (tid < 256) gemm_worker(dsm, 1, tid, b_out, out);
        else           gemm_worker(dsm + HALF_BYTES, 2, tid - 256, b_out, out);
        return;
    }

    // ============ LSTM CTA: warps 0-7 recurrence, warps 8-15 exit ============
    if (tid >= 256) return;

    int b    = blockIdx.x;
    int w    = tid >> 5;
    int lane = tid & 31;
    int kbase = w * 64;
    // matvec row for (gate = lane>>3, elem = lane&7):
    int grow = (lane >> 3) * HID + b * 8 + (lane & 7);

    float4 Wreg[16];
    {
        const float4* wp = (const float4*)(Whh + (size_t)grow * HID + kbase);
#pragma unroll
        for (int i = 0; i < 16; i++) Wreg[i] = wp[i];
    }

    __shared__ float part[2][8][32];
    __shared__ __align__(16) float hbuf[8][64];
    float c_val = 0.f, h_last = 0.f;
    if (lane == 0) c_val = c0[b * 8 + w];    // warp w owns element w

    for (int t = 0; t < T_TOT; t++) {
        // x prefetch for the distributed epilogue: lanes 0-3 of warp w
        // load X(gate=lane, elem=w); independent of h, overlaps the poll.
        float xg = (lane < 4) ? g_X[(size_t)t * G4H + lane * HID + b * 8 + w] : 0.f;

        float ha, hb;
        if (t) {
            const unsigned long long* pp = g_pub + (size_t)(t - 1) * HID + kbase;
            unsigned long long pa, pb;
            for (;;) {
                asm volatile("ld.relaxed.gpu.global.b64 %0, [%1];"
                             : "=l"(pa) : "l"(pp + lane) : "memory");
                asm volatile("ld.relaxed.gpu.global.b64 %0, [%1];"
                             : "=l"(pb) : "l"(pp + 32 + lane) : "memory");
                unsigned ta = (unsigned)(pa >> 32), tb = (unsigned)(pb >> 32);
                if (!__any_sync(0xffffffffu,
                                (ta < (unsigned)t) || (tb < (unsigned)t))) break;
            }
            ha = __uint_as_float((unsigned)pa);
            hb = __uint_as_float((unsigned)pb);
        } else {
            ha = h0[kbase + lane];
            hb = h0[kbase + 32 + lane];
        }

        hbuf[w][lane]      = ha;
        hbuf[w][32 + lane] = hb;
        __syncwarp();

        float a0 = 0.f, a1 = 0.f, a2 = 0.f, a3 = 0.f;
#pragma unroll
        for (int m = 0; m < 16; m++) {
            float4 hv = *(const float4*)&hbuf[w][m * 4];
            a0 = fmaf(Wreg[m].x, hv.x, a0);
            a1 = fmaf(Wreg[m].y, hv.y, a1);
            a2 = fmaf(Wreg[m].z, hv.z, a2);
            a3 = fmaf(Wreg[m].w, hv.w, a3);
        }
        part[t & 1][w][lane] = (a0 + a1) + (a2 + a3);
        NB(3);

        // band release: bar above orders ALL warps' stores from step t-1
        if (w == 0 && lane == 0 && t && (t & 127) == 0) {
            asm volatile("fence.acq_rel.gpu;" ::: "memory");
            asm volatile("st.release.gpu.global.s32 [%0], %1;"
                         :: "l"(&g_done[b * FSTR]), "r"(t) : "memory");
        }

        // distributed epilogue: warp w computes h element w; lanes 0-3 = gates i,f,g,o
        float act = 0.f;
        if (lane < 4) {
            float s = xg;
#pragma unroll
            for (int q2 = 0; q2 < 8; q2++) s += part[t & 1][q2][lane * 8 + w];
            // lanes 0,1,3: sigmoid(s)=0.5*tanh(0.5s)+0.5 ; lane 2: tanh(s)
            float aa = (lane == 2) ? 1.0f : 0.5f;
            float oo = (lane == 2) ? 0.0f : 0.5f;
            act = fmaf(aa, tanh_f(aa * s), oo);   // aa doubles as output scale
        }
        float fi = __shfl_sync(0xffffffffu, act, 0);
        float ff = __shfl_sync(0xffffffffu, act, 1);
        float fg = __shfl_sync(0xffffffffu, act, 2);
        float fo = __shfl_sync(0xffffffffu, act, 3);
        if (lane == 0) {
            c_val = fmaf(ff, c_val, fi * fg);
            float h_new = fo * tanh_f(c_val);
            h_last = h_new;
            size_t idx = (size_t)t * HID + b * 8 + w;
            unsigned long long pk =
                ((unsigned long long)(unsigned)(t + 1) << 32) |
                (unsigned long long)__float_as_uint(h_new);
            asm volatile("st.relaxed.gpu.global.b64 [%0], %1;"
                         :: "l"(&g_pub[idx]), "l"(pk) : "memory");
            __nv_bfloat16 hi = __float2bfloat16(h_new);
            g_Ahi[idx] = hi;
            g_Alo[idx] = __float2bfloat16(h_new - __bfloat162float(hi));
        }
    }
    NB(3);
    // final release: all warps' last-step stores (pub/Ahi/Alo) are bar-ordered
    if (w == 0 && lane == 0) {
        asm volatile("fence.acq_rel.gpu;" ::: "memory");
        asm volatile("st.release.gpu.global.s32 [%0], %1;"
                     :: "l"(&g_done[b * FSTR]), "r"(T_TOT) : "memory");
    }

    if (lane == 0) {
        out_tail[b * 8 + w]       = h_last;
        out_tail[HID + b * 8 + w] = c_val;
    }

    // join the GEMM queue for the tail
    gemm_worker(dsm, 3, tid, b_out, out);
}

// ---------------- launch ----------------
extern "C" void kernel_launch(void* const* d_in, const int* in_sizes, int n_in,
                              void* d_out, int out_size) {
    const int*   seq   = (const int*)d_in[0];
    const float* h0    = (const float*)d_in[1];
    const float* c0    = (const float*)d_in[2];
    const float* embt  = (const float*)d_in[3];
    const float* W_ih  = (const float*)d_in[4];
    const float* W_hh  = (const float*)d_in[5];
    const float* b_ih  = (const float*)d_in[6];
    const float* b_hh  = (const float*)d_in[7];
    const float* W_out = (const float*)d_in[8];
    const float* b_out = (const float*)d_in[9];
    float* out = (float*)d_out;

    float *p_emb, *p_bias, *p_X;
    cudaGetSymbolAddress((void**)&p_emb,  g_emb);
    cudaGetSymbolAddress((void**)&p_bias, g_bias);
    cudaGetSymbolAddress((void**)&p_X,    g_X);

    // K0: gather + bias + state reset
    setup_kernel<<<T_TOT + 8, 256>>>(seq, embt, b_ih, b_hh);

    // K1: X = emb @ W_ih^T + bias
    {
        dim3 grid(G4H / 128, (T_TOT + 127) / 128);
        sgemm_kernel<<<grid, 256>>>(p_emb, W_ih, p_bias, p_X, T_TOT, G4H, EMB);
    }

    // K2: fused recurrence + overlapped band-synchronized logits GEMM + GEMV tail
    cudaFuncSetAttribute(fused_kernel,
                         cudaFuncAttributeMaxDynamicSharedMemorySize, SMEM_K2);
    fused_kernel<<<GRID_K2, 512, SMEM_K2>>>(W_hh, h0, c0, W_out, b_out, out,
                                            out + (size_t)T_TOT * VOCAB);
}

// round 11
// speedup vs baseline: 1.2555x; 1.2555x over previous
#include <cuda_runtime.h>
#include <cuda_bf16.h>

#define SEQLEN  512
#define T_TOT   513
#define EMB     256
#define HID     512
#define G4H     2048
#define VOCAB   32000
#define NLSTM   64
#define NGEMM   84
#define GRID_K2 (NLSTM + NGEMM)   // 148 = one CTA per SM
#define SOS_ID  1
#define FSTR    32                // one 128B line per flag

#define NTILE_N 250
#define NTILES  (5 * NTILE_N)     // bands 0-3: MMA tiles; band 4: GEMV slices

#define KC      32
#define PADW    40
#define TILE_E  (128 * PADW)
#define HALF_BYTES (8 * TILE_E * 2 + 128)
#define SMEM_K2    (2 * HALF_BYTES)

// ---------------- scratch ----------------
__device__ float g_emb[T_TOT * EMB];
__device__ float g_bias[G4H];
__device__ float g_X[T_TOT * G4H];
__device__ unsigned long long g_pub[T_TOT * HID];   // {f32 h, u32 tag=t+1}
__device__ __nv_bfloat16 g_Ahi[T_TOT * HID];
__device__ __nv_bfloat16 g_Alo[T_TOT * HID];
__device__ __nv_bfloat16 g_Whi[VOCAB * HID];
__device__ __nv_bfloat16 g_Wlo[VOCAB * HID];
__device__ int g_done[NLSTM * FSTR];
__device__ int g_qhead;
__device__ int g_cvt;

#define NB(id) asm volatile("bar.sync %0, 256;" :: "r"(id) : "memory")

__device__ __forceinline__ float tanh_f(float x) {
    float y; asm("tanh.approx.f32 %0, %1;" : "=f"(y) : "f"(x)); return y;
}
__device__ __forceinline__ float sigmoid_f(float x) {
    return fmaf(0.5f, tanh_f(0.5f * x), 0.5f);
}

// ---------------- K0: gather emb, bias sum, clear state ----------------
__global__ void setup_kernel(const int* __restrict__ seq,
                             const float* __restrict__ emb_table,
                             const float* __restrict__ b_ih,
                             const float* __restrict__ b_hh) {
    int b = blockIdx.x, t = threadIdx.x;   // blockDim == 256
    if (b < T_TOT) {
        int tok = (b == 0) ? SOS_ID : seq[b - 1];
        g_emb[b * EMB + t] = emb_table[tok * EMB + t];
        if (b == 0) {
            if (t < NLSTM) g_done[t * FSTR] = 0;
            if (t == 64) g_qhead = 0;
            if (t == 65) g_cvt = 0;
        }
    } else {
        int i = (b - T_TOT) * 256 + t;
        g_bias[i] = b_ih[i] + b_hh[i];
    }
    const int NW = T_TOT * HID;
    for (int i = b * 256 + t; i < NW; i += gridDim.x * 256) g_pub[i] = 0ULL;
}

// ---------------- FFMA SGEMM for K1 (small) ----------------
__global__ void __launch_bounds__(256) sgemm_kernel(const float* __restrict__ A,
                                                    const float* __restrict__ B,
                                                    const float* __restrict__ bias,
                                                    float* __restrict__ C,
                                                    int M, int N, int K) {
    __shared__ __align__(16) float As[8][128];
    __shared__ __align__(16) float Bs[8][128];
    int bn = blockIdx.x * 128, bm = blockIdx.y * 128;
    int tid = threadIdx.x;
    int lrow = tid >> 1, lk = (tid & 1) * 4;
    int tx = tid & 15, ty = tid >> 4;

    const float* Aptr = A + (size_t)(bm + lrow) * K + lk;
    const float* Bptr = B + (size_t)(bn + lrow) * K + lk;
    bool aval = (bm + lrow) < M;
    float4 av = aval ? *(const float4*)Aptr : make_float4(0.f, 0.f, 0.f, 0.f);
    float4 bv = *(const float4*)Bptr;

    float acc[8][8];
#pragma unroll
    for (int i = 0; i < 8; i++)
#pragma unroll
        for (int j = 0; j < 8; j++) acc[i][j] = 0.f;

    for (int k0 = 0; k0 < K; k0 += 8) {
        As[lk + 0][lrow] = av.x; As[lk + 1][lrow] = av.y;
        As[lk + 2][lrow] = av.z; As[lk + 3][lrow] = av.w;
        Bs[lk + 0][lrow] = bv.x; Bs[lk + 1][lrow] = bv.y;
        Bs[lk + 2][lrow] = bv.z; Bs[lk + 3][lrow] = bv.w;
        __syncthreads();
        if (k0 + 8 < K) {
            av = aval ? *(const float4*)(Aptr + k0 + 8) : make_float4(0.f, 0.f, 0.f, 0.f);
            bv = *(const float4*)(Bptr + k0 + 8);
        }
#pragma unroll
        for (int k = 0; k < 8; k++) {
            float ar[8], br[8];
            *(float4*)(ar)     = *(const float4*)&As[k][ty * 8];
            *(float4*)(ar + 4) = *(const float4*)&As[k][ty * 8 + 4];
            *(float4*)(br)     = *(const float4*)&Bs[k][tx * 8];
            *(float4*)(br + 4) = *(const float4*)&Bs[k][tx * 8 + 4];
#pragma unroll
            for (int i = 0; i < 8; i++)
#pragma unroll
                for (int j = 0; j < 8; j++)
                    acc[i][j] = fmaf(ar[i], br[j], acc[i][j]);
        }
        __syncthreads();
    }
    float4 bb0 = *(const float4*)&bias[bn + tx * 8];
    float4 bb1 = *(const float4*)&bias[bn + tx * 8 + 4];
#pragma unroll
    for (int i = 0; i < 8; i++) {
        int m = bm + ty * 8 + i;
        if (m < M) {
            float4 o0 = make_float4(acc[i][0] + bb0.x, acc[i][1] + bb0.y,
                                    acc[i][2] + bb0.z, acc[i][3] + bb0.w);
            float4 o1 = make_float4(acc[i][4] + bb1.x, acc[i][5] + bb1.y,
                                    acc[i][6] + bb1.z, acc[i][7] + bb1.w);
            *(float4*)&C[(size_t)m * N + bn + tx * 8]     = o0;
            *(float4*)&C[(size_t)m * N + bn + tx * 8 + 4] = o1;
        }
    }
}

// ---------------- GEMM helpers ----------------
__device__ __forceinline__ void cp_async16(unsigned dst, const void* src, int sz) {
    asm volatile("cp.async.ca.shared.global [%0], [%1], 16, %2;\n"
                 :: "r"(dst), "l"(src), "r"(sz));
}
__device__ __forceinline__ void mma16(float* c, const unsigned* a, const unsigned* b) {
    asm volatile("mma.sync.aligned.m16n8k16.row.col.f32.bf16.bf16.f32 "
                 "{%0,%1,%2,%3}, {%4,%5,%6,%7}, {%8,%9}, {%0,%1,%2,%3};"
                 : "+f"(c[0]), "+f"(c[1]), "+f"(c[2]), "+f"(c[3])
                 : "r"(a[0]), "r"(a[1]), "r"(a[2]), "r"(a[3]),
                   "r"(b[0]), "r"(b[1]));
}

// ---------------- persistent GEMM worker (one 256-thread pipeline) ----------------
__device__ void gemm_worker(char* sm, int bar_id, int htid,
                            const float* __restrict__ bias, float* __restrict__ C) {
    __nv_bfloat16* Ah = (__nv_bfloat16*)sm;
    __nv_bfloat16* Al = Ah + 2 * TILE_E;
    __nv_bfloat16* Bh = Ah + 4 * TILE_E;
    __nv_bfloat16* Bl = Ah + 6 * TILE_E;
    volatile int* q_slot = (volatile int*)(sm + 8 * TILE_E * 2);

    int warp = htid >> 5, lane = htid & 31;
    int wm = warp >> 2, wn = warp & 3;
    int group = lane >> 2, tg = lane & 3;

    if (htid == 0) {
        int v;
        do {
            asm volatile("ld.acquire.gpu.global.s32 %0, [%1];"
                         : "=r"(v) : "l"(&g_cvt) : "memory");
        } while (v < NGEMM);
    }
    NB(bar_id);

    for (;;) {
        if (htid == 0) *q_slot = atomicAdd(&g_qhead, 1);
        NB(bar_id);
        int q = *q_slot;
        if (q >= NTILES) return;
        int band = q / NTILE_N;
        int need = min((band + 1) * 128, T_TOT);

        // band readiness: all 64 lstm CTAs past 'need' steps
        if (htid < 32) {
            int v1, v2;
            do {
                asm volatile("ld.acquire.gpu.global.s32 %0, [%1];"
                             : "=r"(v1) : "l"(&g_done[htid * FSTR]) : "memory");
                asm volatile("ld.acquire.gpu.global.s32 %0, [%1];"
                             : "=r"(v2) : "l"(&g_done[(htid + 32) * FSTR]) : "memory");
            } while (__any_sync(0xffffffffu, (v1 < need) || (v2 < need)));
        }
        NB(bar_id);

        if (band == 4) {
            // ---- GEMV slice: logits row SEQLEN (final h), 128 columns ----
            int col0 = (q - 4 * NTILE_N) * 128;
            float* hsm = (float*)sm;
            for (int i = htid; i < HID; i += 256) {
                unsigned long long p = g_pub[(size_t)SEQLEN * HID + i];
                hsm[i] = __uint_as_float((unsigned)p);
            }
            NB(bar_id);
            int col  = col0 + (htid >> 1);
            int half = htid & 1;
            const __nv_bfloat16* ph = g_Whi + (size_t)col * HID + half * 256;
            const __nv_bfloat16* pl = g_Wlo + (size_t)col * HID + half * 256;
            const float* hh = hsm + half * 256;
            float acc = 0.f;
#pragma unroll 4
            for (int k = 0; k < 256; k += 8) {
                uint4 uh = *(const uint4*)(ph + k);
                uint4 ul = *(const uint4*)(pl + k);
                const unsigned* uhp = &uh.x;
                const unsigned* ulp = &ul.x;
#pragma unroll
                for (int j = 0; j < 4; j++) {
                    float2 fh = __bfloat1622float2(*(const __nv_bfloat162*)&uhp[j]);
                    float2 fl = __bfloat1622float2(*(const __nv_bfloat162*)&ulp[j]);
                    acc = fmaf(fh.x + fl.x, hh[k + 2 * j], acc);
                    acc = fmaf(fh.y + fl.y, hh[k + 2 * j + 1], acc);
                }
            }
            float other = __shfl_down_sync(0xffffffffu, acc, 1);
            if (!half) C[(size_t)SEQLEN * VOCAB + col] = acc + other + bias[col];
            NB(bar_id);   // protect hsm before next item's cp.async
            continue;
        }

        int bn = (q - band * NTILE_N) * 128;
        int bm = band * 128;    // bands 0-3: rows <= 511, always valid

        auto load_stage = [&](int s, int kc) {
#pragma unroll
            for (int i = 0; i < 2; i++) {
                int id  = htid + i * 256;
                int row = id >> 2;
                int kk  = (id & 3) * 8;
                unsigned so = (unsigned)(s * TILE_E + row * PADW + kk) * 2;
                unsigned base = (unsigned)__cvta_generic_to_shared(sm);
                cp_async16(base + so,                  g_Ahi + (size_t)(bm + row) * HID + kc + kk, 16);
                cp_async16(base + so + 2 * TILE_E * 2, g_Alo + (size_t)(bm + row) * HID + kc + kk, 16);
                cp_async16(base + so + 4 * TILE_E * 2, g_Whi + (size_t)(bn + row) * HID + kc + kk, 16);
                cp_async16(base + so + 6 * TILE_E * 2, g_Wlo + (size_t)(bn + row) * HID + kc + kk, 16);
            }
            asm volatile("cp.async.commit_group;\n");
        };

        float acc[4][4][4];
#pragma unroll
        for (int mt = 0; mt < 4; mt++)
#pragma unroll
            for (int nt = 0; nt < 4; nt++)
#pragma unroll
                for (int e = 0; e < 4; e++) acc[mt][nt][e] = 0.f;

        const int NCH = HID / KC;   // 16
        load_stage(0, 0);

        for (int c = 0; c < NCH; c++) {
            if (c + 1 < NCH) {
                load_stage((c + 1) & 1, (c + 1) * KC);
                asm volatile("cp.async.wait_group 1;\n");
            } else {
                asm volatile("cp.async.wait_group 0;\n");
            }
            NB(bar_id);

            int s = c & 1;
#pragma unroll
            for (int ks = 0; ks < 2; ks++) {
                int k0 = ks * 16 + tg * 2;
                unsigned aH[4][4], aL[4][4], bHf[4][2], bLf[4][2];
#pragma unroll
                for (int mt = 0; mt < 4; mt++) {
                    int r0 = (wm * 64 + mt * 16 + group) * PADW + s * TILE_E;
                    aH[mt][0] = *(const unsigned*)&Ah[r0 + k0];
                    aH[mt][1] = *(const unsigned*)&Ah[r0 + 8 * PADW + k0];
                    aH[mt][2] = *(const unsigned*)&Ah[r0 + k0 + 8];
                    aH[mt][3] = *(const unsigned*)&Ah[r0 + 8 * PADW + k0 + 8];
                    aL[mt][0] = *(const unsigned*)&Al[r0 + k0];
                    aL[mt][1] = *(const unsigned*)&Al[r0 + 8 * PADW + k0];
                    aL[mt][2] = *(const unsigned*)&Al[r0 + k0 + 8];
                    aL[mt][3] = *(const unsigned*)&Al[r0 + 8 * PADW + k0 + 8];
                }
#pragma unroll
                for (int nt = 0; nt < 4; nt++) {
                    int c0 = (wn * 32 + nt * 8 + group) * PADW + s * TILE_E;
                    bHf[nt][0] = *(const unsigned*)&Bh[c0 + k0];
                    bHf[nt][1] = *(const unsigned*)&Bh[c0 + k0 + 8];
                    bLf[nt][0] = *(const unsigned*)&Bl[c0 + k0];
                    bLf[nt][1] = *(const unsigned*)&Bl[c0 + k0 + 8];
                }
#pragma unroll
                for (int mt = 0; mt < 4; mt++)
#pragma unroll
                    for (int nt = 0; nt < 4; nt++) {
                        mma16(acc[mt][nt], aH[mt], bHf[nt]);
                        mma16(acc[mt][nt], aH[mt], bLf[nt]);
                        mma16(acc[mt][nt], aL[mt], bHf[nt]);
                    }
            }
            NB(bar_id);
        }

#pragma unroll
        for (int nt = 0; nt < 4; nt++) {
            int col = bn + wn * 32 + nt * 8 + tg * 2;
            float b0 = bias[col], b1 = bias[col + 1];
#pragma unroll
            for (int mt = 0; mt < 4; mt++) {
                int row = bm + wm * 64 + mt * 16 + group;
                float2 o0 = make_float2(acc[mt][nt][0] + b0, acc[mt][nt][1] + b1);
                float2 o1 = make_float2(acc[mt][nt][2] + b0, acc[mt][nt][3] + b1);
                *(float2*)&C[(size_t)row * VOCAB + col]       = o0;
                *(float2*)&C[(size_t)(row + 8) * VOCAB + col] = o1;
            }
        }
    }
}

// ---------------- K2 mega-kernel: recurrence + overlapped logits GEMM ------------
extern __shared__ __align__(16) char dsm[];

__global__ void __launch_bounds__(512, 1) fused_kernel(const float* __restrict__ Whh,
                                                       const float* __restrict__ h0,
                                                       const float* __restrict__ c0,
                                                       const float* __restrict__ Wout,
                                                       const float* __restrict__ b_out,
                                                       float* __restrict__ out,
                                                       float* __restrict__ out_tail) {
    int tid = threadIdx.x;

    if (blockIdx.x >= NLSTM) {
        // ============ GEMM CTA: convert W_out, then two tile pipelines ============
        int cb = blockIdx.x - NLSTM;
        const float4* src = (const float4*)Wout;
        const int total4 = VOCAB * HID / 4;
        for (int i = cb * 512 + tid; i < total4; i += NGEMM * 512) {
            float4 v = src[i];
            __nv_bfloat16 h0b = __float2bfloat16(v.x);
            __nv_bfloat16 h1b = __float2bfloat16(v.y);
            __nv_bfloat16 h2b = __float2bfloat16(v.z);
            __nv_bfloat16 h3b = __float2bfloat16(v.w);
            __nv_bfloat16 l0b = __float2bfloat16(v.x - __bfloat162float(h0b));
            __nv_bfloat16 l1b = __float2bfloat16(v.y - __bfloat162float(h1b));
            __nv_bfloat16 l2b = __float2bfloat16(v.z - __bfloat162float(h2b));
            __nv_bfloat16 l3b = __float2bfloat16(v.w - __bfloat162float(h3b));
            uint2 uh, ul;
            uh.x = ((unsigned)__bfloat16_as_ushort(h1b) << 16) | __bfloat16_as_ushort(h0b);
            uh.y = ((unsigned)__bfloat16_as_ushort(h3b) << 16) | __bfloat16_as_ushort(h2b);
            ul.x = ((unsigned)__bfloat16_as_ushort(l1b) << 16) | __bfloat16_as_ushort(l0b);
            ul.y = ((unsigned)__bfloat16_as_ushort(l3b) << 16) | __bfloat16_as_ushort(l2b);
            *(uint2*)&g_Whi[4 * (size_t)i] = uh;
            *(uint2*)&g_Wlo[4 * (size_t)i] = ul;
        }
        __syncthreads();
        if (tid == 0) {
            asm volatile("fence.acq_rel.gpu;" ::: "memory");
            atomicAdd(&g_cvt, 1);
        }
        if (tid < 256) gemm_worker(dsm, 1, tid, b_out, out);
        else           gemm_worker(dsm + HALF_BYTES, 2, tid - 256, b_out, out);
        return;
    }

    // ============ LSTM CTA: warps 0-7 recurrence, warps 8-15 exit ============
    if (tid >= 256) return;

    int b    = blockIdx.x;
    int w    = tid >> 5;
    int lane = tid & 31;
    int gate = lane >> 3;
    int jj   = lane & 7;
    int grow  = gate * HID + b * 8 + jj;
    int kbase = w * 64;

    float4 Wreg[16];
    {
        const float4* wp = (const float4*)(Whh + (size_t)grow * HID + kbase);
#pragma unroll
        for (int i = 0; i < 16; i++) Wreg[i] = wp[i];
    }

    __shared__ float part[2][8][32];
    __shared__ __align__(16) float hbuf[8][64];   // per-warp h chunk (warp-private)
    float c_val = 0.f, h_last = 0.f;
    if (w == 0 && lane < 8) c_val = c0[b * 8 + lane];

    for (int t = 0; t < T_TOT; t++) {
        float xv = (w == 0) ? g_X[(size_t)t * G4H + grow] : 0.f;

        float ha, hb;
        if (t) {
            const unsigned long long* pp = g_pub + (size_t)(t - 1) * HID + kbase;
            unsigned long long pa, pb;
            for (;;) {
                asm volatile("ld.relaxed.gpu.global.b64 %0, [%1];"
                             : "=l"(pa) : "l"(pp + lane) : "memory");
                asm volatile("ld.relaxed.gpu.global.b64 %0, [%1];"
                             : "=l"(pb) : "l"(pp + 32 + lane) : "memory");
                unsigned ta = (unsigned)(pa >> 32), tb = (unsigned)(pb >> 32);
                if (!__any_sync(0xffffffffu,
                                (ta < (unsigned)t) || (tb < (unsigned)t))) break;
            }
            ha = __uint_as_float((unsigned)pa);
            hb = __uint_as_float((unsigned)pb);
        } else {
            ha = h0[kbase + lane];
            hb = h0[kbase + 32 + lane];
        }

        // warp-private smem broadcast of the h chunk
        hbuf[w][lane]      = ha;
        hbuf[w][32 + lane] = hb;
        __syncwarp();

        float a0 = 0.f, a1 = 0.f, a2 = 0.f, a3 = 0.f;
#pragma unroll
        for (int m = 0; m < 16; m++) {
            float4 hv = *(const float4*)&hbuf[w][m * 4];
            a0 = fmaf(Wreg[m].x, hv.x, a0);
            a1 = fmaf(Wreg[m].y, hv.y, a1);
            a2 = fmaf(Wreg[m].z, hv.z, a2);
            a3 = fmaf(Wreg[m].w, hv.w, a3);
        }
        part[t & 1][w][lane] = (a0 + a1) + (a2 + a3);
        NB(3);

        if (w == 0) {
            float g = xv;
#pragma unroll
            for (int q = 0; q < 8; q++) g += part[t & 1][q][lane];
            float vi = __shfl_sync(0xffffffffu, g, jj);
            float vf = __shfl_sync(0xffffffffu, g, 8 + jj);
            float vg = __shfl_sync(0xffffffffu, g, 16 + jj);
            float vo = __shfl_sync(0xffffffffu, g, 24 + jj);
            if (lane < 8) {
                float fi = sigmoid_f(vi);
                float ff = sigmoid_f(vf);
                float fo = sigmoid_f(vo);
                float fg = tanh_f(vg);
                c_val = ff * c_val + fi * fg;
                float h_new = fo * tanh_f(c_val);
                h_last = h_new;
                size_t idx = (size_t)t * HID + b * 8 + lane;
                unsigned long long pk =
                    ((unsigned long long)(unsigned)(t + 1) << 32) |
                    (unsigned long long)__float_as_uint(h_new);
                asm volatile("st.relaxed.gpu.global.b64 [%0], %1;"
                             :: "l"(&g_pub[idx]), "l"(pk) : "memory");
                __nv_bfloat16 hi = __float2bfloat16(h_new);
                g_Ahi[idx] = hi;
                g_Alo[idx] = __float2bfloat16(h_new - __bfloat162float(hi));
            }
            __syncwarp();
            if (lane == 0 && (((t & 127) == 127) || t == SEQLEN)) {
                asm volatile("fence.acq_rel.gpu;" ::: "memory");
                asm volatile("st.release.gpu.global.s32 [%0], %1;"
                             :: "l"(&g_done[b * FSTR]), "r"(t + 1) : "memory");
            }
        }
    }
    NB(3);

    if (w == 0 && lane < 8) {
        out_tail[b * 8 + lane]       = h_last;
        out_tail[HID + b * 8 + lane] = c_val;
    }

    // join the GEMM queue for the tail
    gemm_worker(dsm, 3, tid, b_out, out);
}

// ---------------- launch ----------------
extern "C" void kernel_launch(void* const* d_in, const int* in_sizes, int n_in,
                              void* d_out, int out_size) {
    const int*   seq   = (const int*)d_in[0];
    const float* h0    = (const float*)d_in[1];
    const float* c0    = (const float*)d_in[2];
    const float* embt  = (const float*)d_in[3];
    const float* W_ih  = (const float*)d_in[4];
    const float* W_hh  = (const float*)d_in[5];
    const float* b_ih  = (const float*)d_in[6];
    const float* b_hh  = (const float*)d_in[7];
    const float* W_out = (const float*)d_in[8];
    const float* b_out = (const float*)d_in[9];
    float* out = (float*)d_out;

    float *p_emb, *p_bias, *p_X;
    cudaGetSymbolAddress((void**)&p_emb,  g_emb);
    cudaGetSymbolAddress((void**)&p_bias, g_bias);
    cudaGetSymbolAddress((void**)&p_X,    g_X);

    // K0: gather + bias + state reset
    setup_kernel<<<T_TOT + 8, 256>>>(seq, embt, b_ih, b_hh);

    // K1: X = emb @ W_ih^T + bias
    {
        dim3 grid(G4H / 128, (T_TOT + 127) / 128);
        sgemm_kernel<<<grid, 256>>>(p_emb, W_ih, p_bias, p_X, T_TOT, G4H, EMB);
    }

    // K2: fused recurrence + overlapped band-synchronized logits GEMM + GEMV tail
    cudaFuncSetAttribute(fused_kernel,
                         cudaFuncAttributeMaxDynamicSharedMemorySize, SMEM_K2);
    fused_kernel<<<GRID_K2, 512, SMEM_K2>>>(W_hh, h0, c0, W_out, b_out, out,
                                            out + (size_t)T_TOT * VOCAB);
}

// round 12
// speedup vs baseline: 1.2634x; 1.0063x over previous
#include <cuda_runtime.h>
#include <cuda_bf16.h>

#define SEQLEN  512
#define T_TOT   513
#define EMB     256
#define HID     512
#define G4H     2048
#define VOCAB   32000
#define NLSTM   64
#define NGEMM   84
#define GRID_K2 (NLSTM + NGEMM)   // 148 = one CTA per SM
#define SOS_ID  1
#define FSTR    32                // one 128B line per flag

#define NTILE_N 250
#define NTILES  (5 * NTILE_N)     // bands 0-3: MMA tiles; band 4: GEMV slices

#define KC      32
#define PADW    40
#define TILE_E  (128 * PADW)
#define HALF_BYTES (8 * TILE_E * 2 + 128)
#define SMEM_K2    (2 * HALF_BYTES)

// ---------------- scratch ----------------
__device__ float g_emb[T_TOT * EMB];
__device__ float g_bias[G4H];
__device__ float g_X[T_TOT * G4H];
__device__ unsigned long long g_pub[T_TOT * HID];   // {f32 h, u32 tag=t+1}
__device__ __nv_bfloat16 g_Ahi[T_TOT * HID];
__device__ __nv_bfloat16 g_Alo[T_TOT * HID];
__device__ __nv_bfloat16 g_Whi[VOCAB * HID];
__device__ __nv_bfloat16 g_Wlo[VOCAB * HID];
__device__ int g_done[NLSTM * FSTR];
__device__ int g_qhead;
__device__ int g_cvt;

#define NB(id) asm volatile("bar.sync %0, 256;" :: "r"(id) : "memory")

__device__ __forceinline__ float tanh_f(float x) {
    float y; asm("tanh.approx.f32 %0, %1;" : "=f"(y) : "f"(x)); return y;
}
__device__ __forceinline__ float sigmoid_f(float x) {
    return fmaf(0.5f, tanh_f(0.5f * x), 0.5f);
}

// ---------------- K0: gather emb, bias sum, clear state ----------------
__global__ void setup_kernel(const int* __restrict__ seq,
                             const float* __restrict__ emb_table,
                             const float* __restrict__ b_ih,
                             const float* __restrict__ b_hh) {
    int b = blockIdx.x, t = threadIdx.x;   // blockDim == 256
    if (b < T_TOT) {
        int tok = (b == 0) ? SOS_ID : seq[b - 1];
        g_emb[b * EMB + t] = emb_table[tok * EMB + t];
        if (b == 0) {
            if (t < NLSTM) g_done[t * FSTR] = 0;
            if (t == 64) g_qhead = 0;
            if (t == 65) g_cvt = 0;
        }
    } else {
        int i = (b - T_TOT) * 256 + t;
        g_bias[i] = b_ih[i] + b_hh[i];
    }
    const int NW = T_TOT * HID;
    for (int i = b * 256 + t; i < NW; i += gridDim.x * 256) g_pub[i] = 0ULL;
}

// ---------------- FFMA SGEMM for K1 (small) ----------------
__global__ void __launch_bounds__(256) sgemm_kernel(const float* __restrict__ A,
                                                    const float* __restrict__ B,
                                                    const float* __restrict__ bias,
                                                    float* __restrict__ C,
                                                    int M, int N, int K) {
    __shared__ __align__(16) float As[8][128];
    __shared__ __align__(16) float Bs[8][128];
    int bn = blockIdx.x * 128, bm = blockIdx.y * 128;
    int tid = threadIdx.x;
    int lrow = tid >> 1, lk = (tid & 1) * 4;
    int tx = tid & 15, ty = tid >> 4;

    const float* Aptr = A + (size_t)(bm + lrow) * K + lk;
    const float* Bptr = B + (size_t)(bn + lrow) * K + lk;
    bool aval = (bm + lrow) < M;
    float4 av = aval ? *(const float4*)Aptr : make_float4(0.f, 0.f, 0.f, 0.f);
    float4 bv = *(const float4*)Bptr;

    float acc[8][8];
#pragma unroll
    for (int i = 0; i < 8; i++)
#pragma unroll
        for (int j = 0; j < 8; j++) acc[i][j] = 0.f;

    for (int k0 = 0; k0 < K; k0 += 8) {
        As[lk + 0][lrow] = av.x; As[lk + 1][lrow] = av.y;
        As[lk + 2][lrow] = av.z; As[lk + 3][lrow] = av.w;
        Bs[lk + 0][lrow] = bv.x; Bs[lk + 1][lrow] = bv.y;
        Bs[lk + 2][lrow] = bv.z; Bs[lk + 3][lrow] = bv.w;
        __syncthreads();
        if (k0 + 8 < K) {
            av = aval ? *(const float4*)(Aptr + k0 + 8) : make_float4(0.f, 0.f, 0.f, 0.f);
            bv = *(const float4*)(Bptr + k0 + 8);
        }
#pragma unroll
        for (int k = 0; k < 8; k++) {
            float ar[8], br[8];
            *(float4*)(ar)     = *(const float4*)&As[k][ty * 8];
            *(float4*)(ar + 4) = *(const float4*)&As[k][ty * 8 + 4];
            *(float4*)(br)     = *(const float4*)&Bs[k][tx * 8];
            *(float4*)(br + 4) = *(const float4*)&Bs[k][tx * 8 + 4];
#pragma unroll
            for (int i = 0; i < 8; i++)
#pragma unroll
                for (int j = 0; j < 8; j++)
                    acc[i][j] = fmaf(ar[i], br[j], acc[i][j]);
        }
        __syncthreads();
    }
    float4 bb0 = *(const float4*)&bias[bn + tx * 8];
    float4 bb1 = *(const float4*)&bias[bn + tx * 8 + 4];
#pragma unroll
    for (int i = 0; i < 8; i++) {
        int m = bm + ty * 8 + i;
        if (m < M) {
            float4 o0 = make_float4(acc[i][0] + bb0.x, acc[i][1] + bb0.y,
                                    acc[i][2] + bb0.z, acc[i][3] + bb0.w);
            float4 o1 = make_float4(acc[i][4] + bb1.x, acc[i][5] + bb1.y,
                                    acc[i][6] + bb1.z, acc[i][7] + bb1.w);
            *(float4*)&C[(size_t)m * N + bn + tx * 8]     = o0;
            *(float4*)&C[(size_t)m * N + bn + tx * 8 + 4] = o1;
        }
    }
}

// ---------------- GEMM helpers ----------------
__device__ __forceinline__ void cp_async16(unsigned dst, const void* src, int sz) {
    asm volatile("cp.async.ca.shared.global [%0], [%1], 16, %2;\n"
                 :: "r"(dst), "l"(src), "r"(sz));
}
__device__ __forceinline__ void mma16(float* c, const unsigned* a, const unsigned* b) {
    asm volatile("mma.sync.aligned.m16n8k16.row.col.f32.bf16.bf16.f32 "
                 "{%0,%1,%2,%3}, {%4,%5,%6,%7}, {%8,%9}, {%0,%1,%2,%3};"
                 : "+f"(c[0]), "+f"(c[1]), "+f"(c[2]), "+f"(c[3])
                 : "r"(a[0]), "r"(a[1]), "r"(a[2]), "r"(a[3]),
                   "r"(b[0]), "r"(b[1]));
}

// ---------------- persistent GEMM worker (one 256-thread pipeline) ----------------
__device__ void gemm_worker(char* sm, int bar_id, int htid,
                            const float* __restrict__ bias, float* __restrict__ C) {
    __nv_bfloat16* Ah = (__nv_bfloat16*)sm;
    __nv_bfloat16* Al = Ah + 2 * TILE_E;
    __nv_bfloat16* Bh = Ah + 4 * TILE_E;
    __nv_bfloat16* Bl = Ah + 6 * TILE_E;
    volatile int* q_slot = (volatile int*)(sm + 8 * TILE_E * 2);

    int warp = htid >> 5, lane = htid & 31;
    int wm = warp >> 2, wn = warp & 3;
    int group = lane >> 2, tg = lane & 3;

    if (htid == 0) {
        int v;
        do {
            asm volatile("ld.acquire.gpu.global.s32 %0, [%1];"
                         : "=r"(v) : "l"(&g_cvt) : "memory");
        } while (v < NGEMM);
    }
    NB(bar_id);

    for (;;) {
        if (htid == 0) *q_slot = atomicAdd(&g_qhead, 1);
        NB(bar_id);
        int q = *q_slot;
        if (q >= NTILES) return;
        int band = q / NTILE_N;
        int need = min((band + 1) * 128, T_TOT);

        // band readiness: all 64 lstm CTAs past 'need' steps
        if (htid < 32) {
            int v1, v2;
            do {
                asm volatile("ld.acquire.gpu.global.s32 %0, [%1];"
                             : "=r"(v1) : "l"(&g_done[htid * FSTR]) : "memory");
                asm volatile("ld.acquire.gpu.global.s32 %0, [%1];"
                             : "=r"(v2) : "l"(&g_done[(htid + 32) * FSTR]) : "memory");
            } while (__any_sync(0xffffffffu, (v1 < need) || (v2 < need)));
        }
        NB(bar_id);

        if (band == 4) {
            // ---- GEMV slice: logits row SEQLEN (final h), 128 columns ----
            int col0 = (q - 4 * NTILE_N) * 128;
            float* hsm = (float*)sm;
            for (int i = htid; i < HID; i += 256) {
                unsigned long long p = g_pub[(size_t)SEQLEN * HID + i];
                hsm[i] = __uint_as_float((unsigned)p);
            }
            NB(bar_id);
            int col  = col0 + (htid >> 1);
            int half = htid & 1;
            const __nv_bfloat16* ph = g_Whi + (size_t)col * HID + half * 256;
            const __nv_bfloat16* pl = g_Wlo + (size_t)col * HID + half * 256;
            const float* hh = hsm + half * 256;
            float acc = 0.f;
#pragma unroll 4
            for (int k = 0; k < 256; k += 8) {
                uint4 uh = *(const uint4*)(ph + k);
                uint4 ul = *(const uint4*)(pl + k);
                const unsigned* uhp = &uh.x;
                const unsigned* ulp = &ul.x;
#pragma unroll
                for (int j = 0; j < 4; j++) {
                    float2 fh = __bfloat1622float2(*(const __nv_bfloat162*)&uhp[j]);
                    float2 fl = __bfloat1622float2(*(const __nv_bfloat162*)&ulp[j]);
                    acc = fmaf(fh.x + fl.x, hh[k + 2 * j], acc);
                    acc = fmaf(fh.y + fl.y, hh[k + 2 * j + 1], acc);
                }
            }
            float other = __shfl_down_sync(0xffffffffu, acc, 1);
            if (!half) C[(size_t)SEQLEN * VOCAB + col] = acc + other + bias[col];
            NB(bar_id);   // protect hsm before next item's cp.async
            continue;
        }

        int bn = (q - band * NTILE_N) * 128;
        int bm = band * 128;    // bands 0-3: rows <= 511, always valid

        auto load_stage = [&](int s, int kc) {
#pragma unroll
            for (int i = 0; i < 2; i++) {
                int id  = htid + i * 256;
                int row = id >> 2;
                int kk  = (id & 3) * 8;
                unsigned so = (unsigned)(s * TILE_E + row * PADW + kk) * 2;
                unsigned base = (unsigned)__cvta_generic_to_shared(sm);
                cp_async16(base + so,                  g_Ahi + (size_t)(bm + row) * HID + kc + kk, 16);
                cp_async16(base + so + 2 * TILE_E * 2, g_Alo + (size_t)(bm + row) * HID + kc + kk, 16);
                cp_async16(base + so + 4 * TILE_E * 2, g_Whi + (size_t)(bn + row) * HID + kc + kk, 16);
                cp_async16(base + so + 6 * TILE_E * 2, g_Wlo + (size_t)(bn + row) * HID + kc + kk, 16);
            }
            asm volatile("cp.async.commit_group;\n");
        };

        float acc[4][4][4];
#pragma unroll
        for (int mt = 0; mt < 4; mt++)
#pragma unroll
            for (int nt = 0; nt < 4; nt++)
#pragma unroll
                for (int e = 0; e < 4; e++) acc[mt][nt][e] = 0.f;

        const int NCH = HID / KC;   // 16
        load_stage(0, 0);

        for (int c = 0; c < NCH; c++) {
            if (c + 1 < NCH) {
                load_stage((c + 1) & 1, (c + 1) * KC);
                asm volatile("cp.async.wait_group 1;\n");
            } else {
                asm volatile("cp.async.wait_group 0;\n");
            }
            NB(bar_id);

            int s = c & 1;
#pragma unroll
            for (int ks = 0; ks < 2; ks++) {
                int k0 = ks * 16 + tg * 2;
                unsigned aH[4][4], aL[4][4], bHf[4][2], bLf[4][2];
#pragma unroll
                for (int mt = 0; mt < 4; mt++) {
                    int r0 = (wm * 64 + mt * 16 + group) * PADW + s * TILE_E;
                    aH[mt][0] = *(const unsigned*)&Ah[r0 + k0];
                    aH[mt][1] = *(const unsigned*)&Ah[r0 + 8 * PADW + k0];
                    aH[mt][2] = *(const unsigned*)&Ah[r0 + k0 + 8];
                    aH[mt][3] = *(const unsigned*)&Ah[r0 + 8 * PADW + k0 + 8];
                    aL[mt][0] = *(const unsigned*)&Al[r0 + k0];
                    aL[mt][1] = *(const unsigned*)&Al[r0 + 8 * PADW + k0];
                    aL[mt][2] = *(const unsigned*)&Al[r0 + k0 + 8];
                    aL[mt][3] = *(const unsigned*)&Al[r0 + 8 * PADW + k0 + 8];
                }
#pragma unroll
                for (int nt = 0; nt < 4; nt++) {
                    int c0 = (wn * 32 + nt * 8 + group) * PADW + s * TILE_E;
                    bHf[nt][0] = *(const unsigned*)&Bh[c0 + k0];
                    bHf[nt][1] = *(const unsigned*)&Bh[c0 + k0 + 8];
                    bLf[nt][0] = *(const unsigned*)&Bl[c0 + k0];
                    bLf[nt][1] = *(const unsigned*)&Bl[c0 + k0 + 8];
                }
#pragma unroll
                for (int mt = 0; mt < 4; mt++)
#pragma unroll
                    for (int nt = 0; nt < 4; nt++) {
                        mma16(acc[mt][nt], aH[mt], bHf[nt]);
                        mma16(acc[mt][nt], aH[mt], bLf[nt]);
                        mma16(acc[mt][nt], aL[mt], bHf[nt]);
                    }
            }
            NB(bar_id);
        }

#pragma unroll
        for (int nt = 0; nt < 4; nt++) {
            int col = bn + wn * 32 + nt * 8 + tg * 2;
            float b0 = bias[col], b1 = bias[col + 1];
#pragma unroll
            for (int mt = 0; mt < 4; mt++) {
                int row = bm + wm * 64 + mt * 16 + group;
                float2 o0 = make_float2(acc[mt][nt][0] + b0, acc[mt][nt][1] + b1);
                float2 o1 = make_float2(acc[mt][nt][2] + b0, acc[mt][nt][3] + b1);
                *(float2*)&C[(size_t)row * VOCAB + col]       = o0;
                *(float2*)&C[(size_t)(row + 8) * VOCAB + col] = o1;
            }
        }
    }
}

// ---------------- K2 mega-kernel: recurrence + overlapped logits GEMM ------------
extern __shared__ __align__(16) char dsm[];

__global__ void __launch_bounds__(512, 1) fused_kernel(const float* __restrict__ Whh,
                                                       const float* __restrict__ h0,
                                                       const float* __restrict__ c0,
                                                       const float* __restrict__ Wout,
                                                       const float* __restrict__ b_out,
                                                       float* __restrict__ out,
                                                       float* __restrict__ out_tail) {
    int tid = threadIdx.x;

    if (blockIdx.x >= NLSTM) {
        // ============ GEMM CTA: convert W_out, then two tile pipelines ============
        int cb = blockIdx.x - NLSTM;
        const float4* src = (const float4*)Wout;
        const int total4 = VOCAB * HID / 4;
        for (int i = cb * 512 + tid; i < total4; i += NGEMM * 512) {
            float4 v = src[i];
            __nv_bfloat16 h0b = __float2bfloat16(v.x);
            __nv_bfloat16 h1b = __float2bfloat16(v.y);
            __nv_bfloat16 h2b = __float2bfloat16(v.z);
            __nv_bfloat16 h3b = __float2bfloat16(v.w);
            __nv_bfloat16 l0b = __float2bfloat16(v.x - __bfloat162float(h0b));
            __nv_bfloat16 l1b = __float2bfloat16(v.y - __bfloat162float(h1b));
            __nv_bfloat16 l2b = __float2bfloat16(v.z - __bfloat162float(h2b));
            __nv_bfloat16 l3b = __float2bfloat16(v.w - __bfloat162float(h3b));
            uint2 uh, ul;
            uh.x = ((unsigned)__bfloat16_as_ushort(h1b) << 16) | __bfloat16_as_ushort(h0b);
            uh.y = ((unsigned)__bfloat16_as_ushort(h3b) << 16) | __bfloat16_as_ushort(h2b);
            ul.x = ((unsigned)__bfloat16_as_ushort(l1b) << 16) | __bfloat16_as_ushort(l0b);
            ul.y = ((unsigned)__bfloat16_as_ushort(l3b) << 16) | __bfloat16_as_ushort(l2b);
            *(uint2*)&g_Whi[4 * (size_t)i] = uh;
            *(uint2*)&g_Wlo[4 * (size_t)i] = ul;
        }
        __syncthreads();
        if (tid == 0) {
            asm volatile("fence.acq_rel.gpu;" ::: "memory");
            atomicAdd(&g_cvt, 1);
        }
        if (tid < 256) gemm_worker(dsm, 1, tid, b_out, out);
        else           gemm_worker(dsm + HALF_BYTES, 2, tid - 256, b_out, out);
        return;
    }

    // ============ LSTM CTA: warps 0-7 recurrence, warps 8-15 exit ============
    if (tid >= 256) return;

    int b    = blockIdx.x;
    int w    = tid >> 5;
    int lane = tid & 31;
    int gate = lane >> 3;
    int jj   = lane & 7;
    int grow  = gate * HID + b * 8 + jj;
    int kbase = w * 64;

    float4 Wreg[16];
    {
        const float4* wp = (const float4*)(Whh + (size_t)grow * HID + kbase);
#pragma unroll
        for (int i = 0; i < 16; i++) Wreg[i] = wp[i];
    }

    __shared__ float part[2][8][32];
    __shared__ __align__(16) float hbuf[8][64];   // per-warp h chunk (warp-private)
    float c_val = 0.f, h_last = 0.f;
    if (w == 0 && lane < 8) c_val = c0[b * 8 + lane];

    for (int t = 0; t < T_TOT; t++) {
        float xv = (w == 0) ? g_X[(size_t)t * G4H + grow] : 0.f;

        float ha, hb;
        if (t) {
            const unsigned long long* pp = g_pub + (size_t)(t - 1) * HID + kbase;
            unsigned long long pa, pb;
            for (;;) {
                asm volatile("ld.relaxed.gpu.global.b64 %0, [%1];"
                             : "=l"(pa) : "l"(pp + lane) : "memory");
                asm volatile("ld.relaxed.gpu.global.b64 %0, [%1];"
                             : "=l"(pb) : "l"(pp + 32 + lane) : "memory");
                unsigned ta = (unsigned)(pa >> 32), tb = (unsigned)(pb >> 32);
                if (!__any_sync(0xffffffffu,
                                (ta < (unsigned)t) || (tb < (unsigned)t))) break;
            }
            ha = __uint_as_float((unsigned)pa);
            hb = __uint_as_float((unsigned)pb);
        } else {
            ha = h0[kbase + lane];
            hb = h0[kbase + 32 + lane];
        }

        // warp-private smem broadcast of the h chunk
        hbuf[w][lane]      = ha;
        hbuf[w][32 + lane] = hb;
        __syncwarp();

        float a0 = 0.f, a1 = 0.f, a2 = 0.f, a3 = 0.f;
#pragma unroll
        for (int m = 0; m < 16; m++) {
            float4 hv = *(const float4*)&hbuf[w][m * 4];
            a0 = fmaf(Wreg[m].x, hv.x, a0);
            a1 = fmaf(Wreg[m].y, hv.y, a1);
            a2 = fmaf(Wreg[m].z, hv.z, a2);
            a3 = fmaf(Wreg[m].w, hv.w, a3);
        }
        part[t & 1][w][lane] = (a0 + a1) + (a2 + a3);
        NB(3);

        if (w == 0) {
            float g = xv;
#pragma unroll
            for (int q = 0; q < 8; q++) g += part[t & 1][q][lane];
            float vi = __shfl_sync(0xffffffffu, g, jj);
            float vf = __shfl_sync(0xffffffffu, g, 8 + jj);
            float vg = __shfl_sync(0xffffffffu, g, 16 + jj);
            float vo = __shfl_sync(0xffffffffu, g, 24 + jj);
            if (lane < 8) {
                float fi = sigmoid_f(vi);
                float ff = sigmoid_f(vf);
                float fo = sigmoid_f(vo);
                float fg = tanh_f(vg);
                c_val = ff * c_val + fi * fg;
                float h_new = fo * tanh_f(c_val);
                h_last = h_new;
                size_t idx = (size_t)t * HID + b * 8 + lane;
                unsigned long long pk =
                    ((unsigned long long)(unsigned)(t + 1) << 32) |
                    (unsigned long long)__float_as_uint(h_new);
                asm volatile("st.relaxed.gpu.global.b64 [%0], %1;"
                             :: "l"(&g_pub[idx]), "l"(pk) : "memory");
                __nv_bfloat16 hi = __float2bfloat16(h_new);
                g_Ahi[idx] = hi;
                g_Alo[idx] = __float2bfloat16(h_new - __bfloat162float(hi));
            }
            __syncwarp();
            if (lane == 0 && (((t & 127) == 127) || t == SEQLEN)) {
                asm volatile("fence.acq_rel.gpu;" ::: "memory");
                asm volatile("st.release.gpu.global.s32 [%0], %1;"
                             :: "l"(&g_done[b * FSTR]), "r"(t + 1) : "memory");
            }
        }
    }
    NB(3);

    if (w == 0 && lane < 8) {
        out_tail[b * 8 + lane]       = h_last;
        out_tail[HID + b * 8 + lane] = c_val;
    }

    // join the GEMM queue for the tail
    gemm_worker(dsm, 3, tid, b_out, out);
}

// ---------------- launch ----------------
extern "C" void kernel_launch(void* const* d_in, const int* in_sizes, int n_in,
                              void* d_out, int out_size) {
    const int*   seq   = (const int*)d_in[0];
    const float* h0    = (const float*)d_in[1];
    const float* c0    = (const float*)d_in[2];
    const float* embt  = (const float*)d_in[3];
    const float* W_ih  = (const float*)d_in[4];
    const float* W_hh  = (const float*)d_in[5];
    const float* b_ih  = (const float*)d_in[6];
    const float* b_hh  = (const float*)d_in[7];
    const float* W_out = (const float*)d_in[8];
    const float* b_out = (const float*)d_in[9];
    float* out = (float*)d_out;

    float *p_emb, *p_bias, *p_X;
    cudaGetSymbolAddress((void**)&p_emb,  g_emb);
    cudaGetSymbolAddress((void**)&p_bias, g_bias);
    cudaGetSymbolAddress((void**)&p_X,    g_X);

    // K0: gather + bias + state reset
    setup_kernel<<<T_TOT + 8, 256>>>(seq, embt, b_ih, b_hh);

    // K1: X = emb @ W_ih^T + bias
    {
        dim3 grid(G4H / 128, (T_TOT + 127) / 128);
        sgemm_kernel<<<grid, 256>>>(p_emb, W_ih, p_bias, p_X, T_TOT, G4H, EMB);
    }

    // K2: fused recurrence + overlapped band-synchronized logits GEMM + GEMV tail
    cudaFuncSetAttribute(fused_kernel,
                         cudaFuncAttributeMaxDynamicSharedMemorySize, SMEM_K2);
    fused_kernel<<<GRID_K2, 512, SMEM_K2>>>(W_hh, h0, c0, W_out, b_out, out,
                                            out + (size_t)T_TOT * VOCAB);
}